// round 16
// baseline (speedup 1.0000x reference)
#include <cuda_runtime.h>
#include <cuda_bf16.h>

#define L      48
#define BATCH  8192
#define EDIM   50
#define HDIM   512
#define VDIM   128
#define G4H    2048
#define KSEG   576         // padded K per segment (512 h + 50 x + 14 pad)
#define AW     1152        // A row width: [hi(576) | lo(576)]
#define WW     1728        // Wext row width: [W_hi | W_lo | W_hi]
#define WOW    1536        // Woext row width: [Wo_hi | Wo_lo | Wo_hi]

// ---------------- device scratch (allocation-free rule) ----------------
__device__ __nv_bfloat16 g_Abf[2][(size_t)BATCH * AW];   // ping-pong [h|x] hi/lo
__device__ __nv_bfloat16 g_Wext[(size_t)G4H * WW];       // gate-interleaved split weight
__device__ __nv_bfloat16 g_Woext[(size_t)VDIM * WOW];    // split output weight
__device__ float g_C[(size_t)BATCH * HDIM];              // cell state fp32
__device__ float g_bc[G4H];                              // fused bias, gate-interleaved

// ---------------- helpers ----------------
__device__ __forceinline__ unsigned smem_u32(const void* p) {
    unsigned a;
    asm("{ .reg .u64 t; cvta.to.shared.u64 t, %1; cvt.u32.u64 %0, t; }" : "=r"(a) : "l"(p));
    return a;
}
__device__ __forceinline__ void cp_async16(unsigned dst, const void* src) {
    asm volatile("cp.async.cg.shared.global [%0], [%1], 16;" :: "r"(dst), "l"(src));
}
__device__ __forceinline__ void cp_commit() { asm volatile("cp.async.commit_group;" ::: "memory"); }
template <int N> __device__ __forceinline__ void cp_wait() {
    asm volatile("cp.async.wait_group %0;" :: "n"(N) : "memory");
}
__device__ __forceinline__ void ldsm4(unsigned& r0, unsigned& r1, unsigned& r2, unsigned& r3,
                                      unsigned addr) {
    asm volatile("ldmatrix.sync.aligned.m8n8.x4.shared.b16 {%0,%1,%2,%3}, [%4];"
                 : "=r"(r0), "=r"(r1), "=r"(r2), "=r"(r3) : "r"(addr));
}
__device__ __forceinline__ void mma16816(float& c0, float& c1, float& c2, float& c3,
                                         unsigned a0, unsigned a1, unsigned a2, unsigned a3,
                                         unsigned b0, unsigned b1) {
    asm volatile("mma.sync.aligned.m16n8k16.row.col.f32.bf16.bf16.f32 "
        "{%0,%1,%2,%3}, {%4,%5,%6,%7}, {%8,%9}, {%0,%1,%2,%3};"
        : "+f"(c0), "+f"(c1), "+f"(c2), "+f"(c3)
        : "r"(a0), "r"(a1), "r"(a2), "r"(a3), "r"(b0), "r"(b1));
}
__device__ __forceinline__ float fsig(float x) {
    return __fdividef(1.0f, 1.0f + __expf(-x));
}
__device__ __forceinline__ float ftanh_fast(float x) {
    float ax = fabsf(x);
    float e  = __expf(-2.0f * ax);
    float t  = __fdividef(1.0f - e, 1.0f + e);
    return copysignf(t, x);
}
__device__ __forceinline__ void split_bf16(float x, __nv_bfloat16& hi, __nv_bfloat16& lo) {
    hi = __float2bfloat16_rn(x);
    lo = __float2bfloat16_rn(x - __bfloat162float(hi));
}

// ---------------- prep kernels (one-time) ----------------
__global__ void prep_w_kernel(const float* __restrict__ W_ih, const float* __restrict__ W_hh) {
    long long idx = (long long)blockIdx.x * blockDim.x + threadIdx.x;
    if (idx >= (long long)G4H * WW) return;
    int n = (int)(idx / WW), k = (int)(idx - (long long)n * WW);
    int seg = k / KSEG, kk = k - seg * KSEG;
    int j = n >> 2, g = n & 3;
    int r = g * HDIM + j;
    float w = 0.0f;
    if (kk < HDIM)            w = W_hh[(size_t)r * HDIM + kk];
    else if (kk < HDIM+EDIM)  w = W_ih[(size_t)r * EDIM + (kk - HDIM)];
    __nv_bfloat16 hi, lo; split_bf16(w, hi, lo);
    g_Wext[idx] = (seg == 1) ? lo : hi;
}
__global__ void prep_wo_kernel(const float* __restrict__ W_out) {
    int idx = blockIdx.x * blockDim.x + threadIdx.x;
    if (idx >= VDIM * WOW) return;
    int n = idx / WOW, k = idx - n * WOW;
    int seg = k / HDIM, kk = k - seg * HDIM;
    float w = W_out[(size_t)n * HDIM + kk];
    __nv_bfloat16 hi, lo; split_bf16(w, hi, lo);
    g_Woext[idx] = (seg == 1) ? lo : hi;
}
__global__ void prep_bc_kernel(const float* __restrict__ b_ih, const float* __restrict__ b_hh) {
    int n = blockIdx.x * blockDim.x + threadIdx.x;
    if (n >= G4H) return;
    int j = n >> 2, g = n & 3, r = g * HDIM + j;
    g_bc[n] = b_ih[r] + b_hh[r];
}
__global__ void init_kernel(const float* __restrict__ h0, const float* __restrict__ c0) {
    int idx = blockIdx.x * blockDim.x + threadIdx.x;
    if (idx >= BATCH * HDIM) return;
    int b = idx >> 9, j = idx & (HDIM - 1);
    __nv_bfloat16 hi, lo; split_bf16(h0[idx], hi, lo);
    g_Abf[0][(size_t)b * AW + j] = hi;
    g_Abf[0][(size_t)b * AW + KSEG + j] = lo;
    g_C[idx] = c0[idx];
}
__global__ void xcopy_kernel(const int* __restrict__ input, const float* __restrict__ emb, int t) {
    int idx = blockIdx.x * blockDim.x + threadIdx.x;
    if (idx >= BATCH * EDIM) return;
    int b = idx / EDIM, e = idx - b * EDIM;
    int tok = input[(size_t)t * BATCH + b];
    __nv_bfloat16 hi, lo; split_bf16(emb[(size_t)tok * EDIM + e], hi, lo);
    g_Abf[t & 1][(size_t)b * AW + HDIM + e] = hi;
    g_Abf[t & 1][(size_t)b * AW + KSEG + HDIM + e] = lo;
}

// ---------------- gates MMA kernel (warp-level mma.sync, bf16) ----------------
// CTA tile 128x128, K-tile 32, 4-stage cp.async pipeline.
// SMEM rows padded to 40 bf16 (80B) for conflict-free ldmatrix.
// Stage block 20480B = A(128x80) + B(128x80). 4 stages = 81920B.
// Epilogue reuses smem: gates fp32 [128][132] = 67584B < 81920.
#define G_TILES    54            // 1728/32
#define G_STBLK    20480
#define GS_SMEM    81920
#define GEPI_P     132           // gates smem pitch (floats)

__device__ __forceinline__ void gates_fill(unsigned sb, int tid, int brow, int bcol,
                                           const __nv_bfloat16* Abuf, int stage, int tile) {
    const int p = tile / 18, kk = tile - p * 18;
    const int acol = ((p == 2) ? KSEG : 0) + kk * 32;
    const int wcol = p * KSEG + kk * 32;
    const unsigned aBase = sb + stage * G_STBLK;
    const unsigned bBase = aBase + 10240u;
#pragma unroll
    for (int i = 0; i < 4; i++) {
        int cid = tid + (i << 8);            // 0..1023
        int ch = cid & 3;                    // 16B chunk (8 bf16)
        if (cid < 512) {
            int r = cid >> 2;                // 0..127
            cp_async16(aBase + r * 80 + ch * 16,
                       Abuf + (size_t)(brow + r) * AW + acol + ch * 8);
        } else {
            int r = (cid - 512) >> 2;
            cp_async16(bBase + r * 80 + ch * 16,
                       g_Wext + (size_t)(bcol + r) * WW + wcol + ch * 8);
        }
    }
    cp_commit();
}

__global__ void __launch_bounds__(256, 2) gates_mma_kernel(int par, int nextT,
                                                           const int* __restrict__ input,
                                                           const float* __restrict__ emb) {
    extern __shared__ char smem[];
    const unsigned sb = smem_u32(smem);
    const int tid = threadIdx.x, wid = tid >> 5, lane = tid & 31;
    const int warp_m = wid >> 2, warp_n = wid & 3;     // 2x4 warp grid, warp tile 64x32
    const int bcol = blockIdx.x << 7;                  // gate cols
    const int brow = blockIdx.y << 7;                  // batch rows
    const __nv_bfloat16* Abuf = g_Abf[par];
    __nv_bfloat16* Anext = g_Abf[par ^ 1];

    float acc[4][4][4];
#pragma unroll
    for (int i = 0; i < 4; i++)
#pragma unroll
        for (int j = 0; j < 4; j++)
#pragma unroll
            for (int q = 0; q < 4; q++) acc[i][j][q] = 0.0f;

    gates_fill(sb, tid, brow, bcol, Abuf, 0, 0);
    gates_fill(sb, tid, brow, bcol, Abuf, 1, 1);
    gates_fill(sb, tid, brow, bcol, Abuf, 2, 2);

    const int lrow = lane & 15;
    const int lkb  = (lane >> 4) * 16;     // byte offset of k-half (8 bf16)

    for (int t = 0; t < G_TILES; t++) {
        if (t >= G_TILES - 1)      cp_wait<0>();
        else if (t >= G_TILES - 2) cp_wait<1>();
        else                       cp_wait<2>();
        __syncthreads();
        int f = t + 3;
        if (f < G_TILES) gates_fill(sb, tid, brow, bcol, Abuf, f & 3, f);

        const int s = t & 3;
        const unsigned aBase = sb + s * G_STBLK;
        const unsigned bBase = aBase + 10240u;
#pragma unroll
        for (int ks = 0; ks < 2; ks++) {
            const unsigned koff = ks * 32 + lkb;       // bytes within 80B row
            unsigned a[4][4], b[2][4];
#pragma unroll
            for (int mt = 0; mt < 4; mt++)
                ldsm4(a[mt][0], a[mt][1], a[mt][2], a[mt][3],
                      aBase + (warp_m * 64 + mt * 16 + lrow) * 80 + koff);
#pragma unroll
            for (int bt = 0; bt < 2; bt++)
                ldsm4(b[bt][0], b[bt][1], b[bt][2], b[bt][3],
                      bBase + (warp_n * 32 + bt * 16 + lrow) * 80 + koff);
#pragma unroll
            for (int mt = 0; mt < 4; mt++)
#pragma unroll
                for (int nt = 0; nt < 4; nt++) {
                    int bt = nt >> 1, sel = nt & 1;
                    mma16816(acc[mt][nt][0], acc[mt][nt][1], acc[mt][nt][2], acc[mt][nt][3],
                             a[mt][0], a[mt][1], a[mt][2], a[mt][3],
                             b[bt][sel], b[bt][sel + 2]);
                }
        }
    }

    // stash gates to smem (reuse pipeline smem), then fused LSTM epilogue
    __syncthreads();
    float* gsm = (float*)smem;
    const int row0 = lane >> 2, colq = (lane & 3) * 2;
#pragma unroll
    for (int mt = 0; mt < 4; mt++)
#pragma unroll
        for (int nt = 0; nt < 4; nt++) {
            int rs = warp_m * 64 + mt * 16 + row0;
            int cs = warp_n * 32 + nt * 8 + colq;
            *(float2*)&gsm[rs * GEPI_P + cs]       = make_float2(acc[mt][nt][0], acc[mt][nt][1]);
            *(float2*)&gsm[(rs + 8) * GEPI_P + cs] = make_float2(acc[mt][nt][2], acc[mt][nt][3]);
        }
    __syncthreads();

    {
        const int r = tid >> 1, half = tid & 1;
        const int grow = brow + r;
        const float* gr = gsm + r * GEPI_P + half * 64;
        const float* bcp = g_bc + bcol + half * 64;
        const int jbase = (bcol >> 2) + half * 16;
        float* cptr = g_C + (size_t)grow * HDIM + jbase;
        float cv[16];
#pragma unroll
        for (int q = 0; q < 4; q++) *(float4*)&cv[4 * q] = *(const float4*)&cptr[4 * q];
        union { __nv_bfloat16 b[16]; uint4 v[2]; } Hh, Hl;
#pragma unroll
        for (int jj = 0; jj < 16; jj++) {
            float gi = fsig(gr[4 * jj + 0] + bcp[4 * jj + 0]);
            float gf = fsig(gr[4 * jj + 1] + bcp[4 * jj + 1]);
            float gg = ftanh_fast(gr[4 * jj + 2] + bcp[4 * jj + 2]);
            float go = fsig(gr[4 * jj + 3] + bcp[4 * jj + 3]);
            float cn = gf * cv[jj] + gi * gg;
            cv[jj] = cn;
            float h = go * ftanh_fast(cn);
            split_bf16(h, Hh.b[jj], Hl.b[jj]);
        }
#pragma unroll
        for (int q = 0; q < 4; q++) *(float4*)&cptr[4 * q] = *(const float4*)&cv[4 * q];
        *(uint4*)&Anext[(size_t)grow * AW + jbase]            = Hh.v[0];
        *(uint4*)&Anext[(size_t)grow * AW + jbase + 8]        = Hh.v[1];
        *(uint4*)&Anext[(size_t)grow * AW + KSEG + jbase]     = Hl.v[0];
        *(uint4*)&Anext[(size_t)grow * AW + KSEG + jbase + 8] = Hl.v[1];

        // fused xcopy for step t+1: one CTA column writes x_{t+1} into Anext
        if (blockIdx.x == 0 && nextT < L) {
            int tok = input[(size_t)nextT * BATCH + grow];
            const float* ev = emb + (size_t)tok * EDIM + half * 25;
            __nv_bfloat16* xh = Anext + (size_t)grow * AW + HDIM + half * 25;
            __nv_bfloat16* xl = xh + KSEG;
#pragma unroll
            for (int e = 0; e < 25; e++) {
                __nv_bfloat16 hi, lo; split_bf16(ev[e], hi, lo);
                xh[e] = hi; xl[e] = lo;
            }
        }
    }
}

// ---------------- output projection MMA kernel ----------------
// CTA tile 64x128 (N=V=128), K-tile 32, 4 stages. Grid = BATCH/64 = 128.
// Stage block 15360B = A(64x80) + B(128x80). 4 stages = 61440B.
#define O_TILES    48            // 1536/32
#define O_STBLK    15360
#define OS_SMEM    61440

__device__ __forceinline__ void out_fill(unsigned sb, int tid, int brow,
                                         const __nv_bfloat16* Abuf, int stage, int tile) {
    const int p = tile / 16, kk = tile - p * 16;
    const int acol = ((p == 2) ? KSEG : 0) + kk * 32;
    const int wcol = p * HDIM + kk * 32;
    const unsigned aBase = sb + stage * O_STBLK;
    const unsigned bBase = aBase + 5120u;
#pragma unroll
    for (int i = 0; i < 3; i++) {
        int cid = tid + (i << 8);            // 0..767
        int ch = cid & 3;
        if (cid < 256) {
            int r = cid >> 2;                // 0..63
            cp_async16(aBase + r * 80 + ch * 16,
                       Abuf + (size_t)(brow + r) * AW + acol + ch * 8);
        } else {
            int r = (cid - 256) >> 2;        // 0..127
            cp_async16(bBase + r * 80 + ch * 16,
                       g_Woext + (size_t)r * WOW + wcol + ch * 8);
        }
    }
    cp_commit();
}

__global__ void __launch_bounds__(256, 2) out_mma_kernel(int step, int par,
                                                         const float* __restrict__ bout,
                                                         float* __restrict__ out) {
    extern __shared__ char smem[];
    const unsigned sb = smem_u32(smem);
    const int tid = threadIdx.x, wid = tid >> 5, lane = tid & 31;
    const int warp_m = wid >> 2, warp_n = wid & 3;     // warp tile 32x32
    const int brow = blockIdx.x << 6;
    const __nv_bfloat16* Abuf = g_Abf[par];

    float acc[2][4][4];
#pragma unroll
    for (int i = 0; i < 2; i++)
#pragma unroll
        for (int j = 0; j < 4; j++)
#pragma unroll
            for (int q = 0; q < 4; q++) acc[i][j][q] = 0.0f;

    out_fill(sb, tid, brow, Abuf, 0, 0);
    out_fill(sb, tid, brow, Abuf, 1, 1);
    out_fill(sb, tid, brow, Abuf, 2, 2);

    const int lrow = lane & 15;
    const int lkb  = (lane >> 4) * 16;

    for (int t = 0; t < O_TILES; t++) {
        if (t >= O_TILES - 1)      cp_wait<0>();
        else if (t >= O_TILES - 2) cp_wait<1>();
        else                       cp_wait<2>();
        __syncthreads();
        int f = t + 3;
        if (f < O_TILES) out_fill(sb, tid, brow, Abuf, f & 3, f);

        const int s = t & 3;
        const unsigned aBase = sb + s * O_STBLK;
        const unsigned bBase = aBase + 5120u;
#pragma unroll
        for (int ks = 0; ks < 2; ks++) {
            const unsigned koff = ks * 32 + lkb;
            unsigned a[2][4], b[2][4];
#pragma unroll
            for (int mt = 0; mt < 2; mt++)
                ldsm4(a[mt][0], a[mt][1], a[mt][2], a[mt][3],
                      aBase + (warp_m * 32 + mt * 16 + lrow) * 80 + koff);
#pragma unroll
            for (int bt = 0; bt < 2; bt++)
                ldsm4(b[bt][0], b[bt][1], b[bt][2], b[bt][3],
                      bBase + (warp_n * 32 + bt * 16 + lrow) * 80 + koff);
#pragma unroll
            for (int mt = 0; mt < 2; mt++)
#pragma unroll
                for (int nt = 0; nt < 4; nt++) {
                    int bt = nt >> 1, sel = nt & 1;
                    mma16816(acc[mt][nt][0], acc[mt][nt][1], acc[mt][nt][2], acc[mt][nt][3],
                             a[mt][0], a[mt][1], a[mt][2], a[mt][3],
                             b[bt][sel], b[bt][sel + 2]);
                }
        }
    }

    // direct epilogue: bias + store
    const int row0 = lane >> 2, colq = (lane & 3) * 2;
    float* dstbase = out + (size_t)step * BATCH * VDIM;
#pragma unroll
    for (int mt = 0; mt < 2; mt++)
#pragma unroll
        for (int nt = 0; nt < 4; nt++) {
            int rs = brow + warp_m * 32 + mt * 16 + row0;
            int cs = warp_n * 32 + nt * 8 + colq;
            float2 bv = *(const float2*)&bout[cs];
            *(float2*)&dstbase[(size_t)rs * VDIM + cs] =
                make_float2(acc[mt][nt][0] + bv.x, acc[mt][nt][1] + bv.y);
            *(float2*)&dstbase[(size_t)(rs + 8) * VDIM + cs] =
                make_float2(acc[mt][nt][2] + bv.x, acc[mt][nt][3] + bv.y);
        }
}

// ---------------- tail: hT, cT ----------------
__global__ void final_kernel(float* __restrict__ out) {
    int idx = blockIdx.x * blockDim.x + threadIdx.x;
    if (idx >= BATCH * HDIM) return;
    int b = idx >> 9, j = idx & (HDIM - 1);
    size_t base = (size_t)L * BATCH * VDIM;
    float h = __bfloat162float(g_Abf[0][(size_t)b * AW + j]) +
              __bfloat162float(g_Abf[0][(size_t)b * AW + KSEG + j]);
    out[base + idx] = h;
    out[base + (size_t)BATCH * HDIM + idx] = g_C[idx];
}

// ---------------- launch ----------------
extern "C" void kernel_launch(void* const* d_in, const int* in_sizes, int n_in,
                              void* d_out, int out_size) {
    const int*   input = (const int*)d_in[0];
    const float* h0    = (const float*)d_in[1];
    const float* c0    = (const float*)d_in[2];
    const float* emb   = (const float*)d_in[3];
    const float* W_ih  = (const float*)d_in[4];
    const float* W_hh  = (const float*)d_in[5];
    const float* b_ih  = (const float*)d_in[6];
    const float* b_hh  = (const float*)d_in[7];
    const float* W_out = (const float*)d_in[8];
    const float* b_out = (const float*)d_in[9];
    float* out = (float*)d_out;

    cudaFuncSetAttribute(gates_mma_kernel, cudaFuncAttributeMaxDynamicSharedMemorySize, GS_SMEM);
    cudaFuncSetAttribute(out_mma_kernel,   cudaFuncAttributeMaxDynamicSharedMemorySize, OS_SMEM);

    long long wtot = (long long)G4H * WW;
    prep_w_kernel<<<(unsigned)((wtot + 255) / 256), 256>>>(W_ih, W_hh);
    prep_wo_kernel<<<(VDIM * WOW + 255) / 256, 256>>>(W_out);
    prep_bc_kernel<<<(G4H + 255) / 256, 256>>>(b_ih, b_hh);
    init_kernel<<<(BATCH * HDIM + 255) / 256, 256>>>(h0, c0);
    xcopy_kernel<<<(BATCH * EDIM + 255) / 256, 256>>>(input, emb, 0);   // x_0 only

    dim3 ggrid(G4H / 128, BATCH / 128);     // (16, 64)
    for (int t = 0; t < L; t++) {
        gates_mma_kernel<<<ggrid, 256, GS_SMEM>>>(t & 1, t + 1, input, emb);
        out_mma_kernel<<<BATCH / 64, 256, OS_SMEM>>>(t, (t + 1) & 1, b_out, out);
    }
    final_kernel<<<(BATCH * HDIM + 255) / 256, 256>>>(out);
}

// round 17
// speedup vs baseline: 1.0274x; 1.0274x over previous
#include <cuda_runtime.h>
#include <cuda_bf16.h>

#define L      48
#define BATCH  8192
#define EDIM   50
#define HDIM   512
#define VDIM   128
#define G4H    2048
#define KSEG   576         // padded K per segment (512 h + 50 x + 14 pad)
#define AW     1152        // A row width: [hi(576) | lo(576)]
#define WW     1728        // Wext row width: [W_hi | W_lo | W_hi]
#define WOW    1536        // Woext row width: [Wo_hi | Wo_lo | Wo_hi]

// ---------------- device scratch (allocation-free rule) ----------------
__device__ __nv_bfloat16 g_Abf[2][(size_t)BATCH * AW];   // ping-pong [h|x] hi/lo
__device__ __nv_bfloat16 g_Wext[(size_t)G4H * WW];       // gate-interleaved split weight
__device__ __nv_bfloat16 g_Woext[(size_t)VDIM * WOW];    // split output weight
__device__ float g_C[(size_t)BATCH * HDIM];              // cell state fp32
__device__ float g_bc[G4H];                              // fused bias, gate-interleaved

// ---------------- helpers ----------------
__device__ __forceinline__ unsigned smem_u32(const void* p) {
    unsigned a;
    asm("{ .reg .u64 t; cvta.to.shared.u64 t, %1; cvt.u32.u64 %0, t; }" : "=r"(a) : "l"(p));
    return a;
}
__device__ __forceinline__ void cp_async16(unsigned dst, const void* src) {
    asm volatile("cp.async.cg.shared.global [%0], [%1], 16;" :: "r"(dst), "l"(src));
}
__device__ __forceinline__ void cp_commit() { asm volatile("cp.async.commit_group;" ::: "memory"); }
template <int N> __device__ __forceinline__ void cp_wait() {
    asm volatile("cp.async.wait_group %0;" :: "n"(N) : "memory");
}
__device__ __forceinline__ void ldsm4(unsigned& r0, unsigned& r1, unsigned& r2, unsigned& r3,
                                      unsigned addr) {
    asm volatile("ldmatrix.sync.aligned.m8n8.x4.shared.b16 {%0,%1,%2,%3}, [%4];"
                 : "=r"(r0), "=r"(r1), "=r"(r2), "=r"(r3) : "r"(addr));
}
__device__ __forceinline__ void mma16816(float& c0, float& c1, float& c2, float& c3,
                                         unsigned a0, unsigned a1, unsigned a2, unsigned a3,
                                         unsigned b0, unsigned b1) {
    asm volatile("mma.sync.aligned.m16n8k16.row.col.f32.bf16.bf16.f32 "
        "{%0,%1,%2,%3}, {%4,%5,%6,%7}, {%8,%9}, {%0,%1,%2,%3};"
        : "+f"(c0), "+f"(c1), "+f"(c2), "+f"(c3)
        : "r"(a0), "r"(a1), "r"(a2), "r"(a3), "r"(b0), "r"(b1));
}
__device__ __forceinline__ float fsig(float x) {
    return __fdividef(1.0f, 1.0f + __expf(-x));
}
__device__ __forceinline__ float ftanh_fast(float x) {
    float ax = fabsf(x);
    float e  = __expf(-2.0f * ax);
    float t  = __fdividef(1.0f - e, 1.0f + e);
    return copysignf(t, x);
}
__device__ __forceinline__ void split_bf16(float x, __nv_bfloat16& hi, __nv_bfloat16& lo) {
    hi = __float2bfloat16_rn(x);
    lo = __float2bfloat16_rn(x - __bfloat162float(hi));
}

// ---------------- merged one-time prep (single launch to steer ncu onto gates) ----------
__global__ void prep_all_kernel(const float* __restrict__ W_ih, const float* __restrict__ W_hh,
                                const float* __restrict__ W_out,
                                const float* __restrict__ b_ih, const float* __restrict__ b_hh) {
    long long idx = (long long)blockIdx.x * blockDim.x + threadIdx.x;
    // part 1: gate weight (G4H x WW)
    if (idx < (long long)G4H * WW) {
        int n = (int)(idx / WW), k = (int)(idx - (long long)n * WW);
        int seg = k / KSEG, kk = k - seg * KSEG;
        int j = n >> 2, g = n & 3;
        int r = g * HDIM + j;
        float w = 0.0f;
        if (kk < HDIM)            w = W_hh[(size_t)r * HDIM + kk];
        else if (kk < HDIM+EDIM)  w = W_ih[(size_t)r * EDIM + (kk - HDIM)];
        __nv_bfloat16 hi, lo; split_bf16(w, hi, lo);
        g_Wext[idx] = (seg == 1) ? lo : hi;
    }
    // part 2: output weight (VDIM x WOW)
    if (idx < (long long)VDIM * WOW) {
        int n = (int)(idx / WOW), k = (int)(idx - (long long)n * WOW);
        int seg = k / HDIM, kk = k - seg * HDIM;
        float w = W_out[(size_t)n * HDIM + kk];
        __nv_bfloat16 hi, lo; split_bf16(w, hi, lo);
        g_Woext[idx] = (seg == 1) ? lo : hi;
    }
    // part 3: fused bias
    if (idx < G4H) {
        int n = (int)idx;
        int j = n >> 2, g = n & 3, r = g * HDIM + j;
        g_bc[n] = b_ih[r] + b_hh[r];
    }
}
__global__ void init_kernel(const float* __restrict__ h0, const float* __restrict__ c0) {
    int idx = blockIdx.x * blockDim.x + threadIdx.x;
    if (idx >= BATCH * HDIM) return;
    int b = idx >> 9, j = idx & (HDIM - 1);
    __nv_bfloat16 hi, lo; split_bf16(h0[idx], hi, lo);
    g_Abf[0][(size_t)b * AW + j] = hi;
    g_Abf[0][(size_t)b * AW + KSEG + j] = lo;
    g_C[idx] = c0[idx];
}
__global__ void xcopy_kernel(const int* __restrict__ input, const float* __restrict__ emb, int t) {
    int idx = blockIdx.x * blockDim.x + threadIdx.x;
    if (idx >= BATCH * EDIM) return;
    int b = idx / EDIM, e = idx - b * EDIM;
    int tok = input[(size_t)t * BATCH + b];
    __nv_bfloat16 hi, lo; split_bf16(emb[(size_t)tok * EDIM + e], hi, lo);
    g_Abf[t & 1][(size_t)b * AW + HDIM + e] = hi;
    g_Abf[t & 1][(size_t)b * AW + KSEG + HDIM + e] = lo;
}

// ---------------- gates MMA kernel (warp-level mma.sync, bf16) ----------------
// CTA tile 128x128, K-tile 32, 3-stage cp.async pipeline.
// SMEM rows padded to 40 bf16 (80B) for conflict-free ldmatrix.
// Stage block 20480B = A(128x80)+B(128x80); 3 stages = 61440B.
// Epilogue reuses smem: gates fp32 [128][132] = 67584B -> GS_SMEM.
#define G_TILES    54            // 1728/32
#define G_STBLK    20480
#define GS_SMEM    67584
#define GEPI_P     132           // gates smem pitch (floats)

__device__ __forceinline__ void gates_fill(unsigned sb, int tid, int brow, int bcol,
                                           const __nv_bfloat16* Abuf, int stage, int tile) {
    const int p = tile / 18, kk = tile - p * 18;
    const int acol = ((p == 2) ? KSEG : 0) + kk * 32;
    const int wcol = p * KSEG + kk * 32;
    const unsigned aBase = sb + stage * G_STBLK;
    const unsigned bBase = aBase + 10240u;
#pragma unroll
    for (int i = 0; i < 4; i++) {
        int cid = tid + (i << 8);            // 0..1023
        int ch = cid & 3;                    // 16B chunk (8 bf16)
        if (cid < 512) {
            int r = cid >> 2;                // 0..127
            cp_async16(aBase + r * 80 + ch * 16,
                       Abuf + (size_t)(brow + r) * AW + acol + ch * 8);
        } else {
            int r = (cid - 512) >> 2;
            cp_async16(bBase + r * 80 + ch * 16,
                       g_Wext + (size_t)(bcol + r) * WW + wcol + ch * 8);
        }
    }
    cp_commit();
}

__global__ void __launch_bounds__(256, 2) gates_mma_kernel(int par) {
    extern __shared__ char smem[];
    const unsigned sb = smem_u32(smem);
    const int tid = threadIdx.x, wid = tid >> 5, lane = tid & 31;
    const int warp_m = wid >> 2, warp_n = wid & 3;     // 2x4 warp grid, warp tile 64x32
    const int bcol = blockIdx.x << 7;                  // gate cols
    const int brow = blockIdx.y << 7;                  // batch rows
    const __nv_bfloat16* Abuf = g_Abf[par];
    __nv_bfloat16* Anext = g_Abf[par ^ 1];

    float acc[4][4][4];
#pragma unroll
    for (int i = 0; i < 4; i++)
#pragma unroll
        for (int j = 0; j < 4; j++)
#pragma unroll
            for (int q = 0; q < 4; q++) acc[i][j][q] = 0.0f;

    gates_fill(sb, tid, brow, bcol, Abuf, 0, 0);
    gates_fill(sb, tid, brow, bcol, Abuf, 1, 1);

    const int lrow = lane & 15;
    const int lkb  = (lane >> 4) * 16;     // byte offset of k-half (8 bf16)

    for (int t = 0; t < G_TILES; t++) {
        if (t == G_TILES - 1) cp_wait<0>(); else cp_wait<1>();
        __syncthreads();
        int f = t + 2;
        if (f < G_TILES) gates_fill(sb, tid, brow, bcol, Abuf, f % 3, f);

        const int s = t % 3;
        const unsigned aBase = sb + s * G_STBLK;
        const unsigned bBase = aBase + 10240u;
#pragma unroll
        for (int ks = 0; ks < 2; ks++) {
            const unsigned koff = ks * 32 + lkb;       // bytes within 80B row
            unsigned a[4][4], b[2][4];
#pragma unroll
            for (int mt = 0; mt < 4; mt++)
                ldsm4(a[mt][0], a[mt][1], a[mt][2], a[mt][3],
                      aBase + (warp_m * 64 + mt * 16 + lrow) * 80 + koff);
#pragma unroll
            for (int bt = 0; bt < 2; bt++)
                ldsm4(b[bt][0], b[bt][1], b[bt][2], b[bt][3],
                      bBase + (warp_n * 32 + bt * 16 + lrow) * 80 + koff);
#pragma unroll
            for (int mt = 0; mt < 4; mt++)
#pragma unroll
                for (int nt = 0; nt < 4; nt++) {
                    int bt = nt >> 1, sel = nt & 1;
                    mma16816(acc[mt][nt][0], acc[mt][nt][1], acc[mt][nt][2], acc[mt][nt][3],
                             a[mt][0], a[mt][1], a[mt][2], a[mt][3],
                             b[bt][sel], b[bt][sel + 2]);
                }
        }
    }

    // stash gates to smem (reuse pipeline smem), then fused LSTM epilogue
    __syncthreads();
    float* gsm = (float*)smem;
    const int row0 = lane >> 2, colq = (lane & 3) * 2;
#pragma unroll
    for (int mt = 0; mt < 4; mt++)
#pragma unroll
        for (int nt = 0; nt < 4; nt++) {
            int rs = warp_m * 64 + mt * 16 + row0;
            int cs = warp_n * 32 + nt * 8 + colq;
            *(float2*)&gsm[rs * GEPI_P + cs]       = make_float2(acc[mt][nt][0], acc[mt][nt][1]);
            *(float2*)&gsm[(rs + 8) * GEPI_P + cs] = make_float2(acc[mt][nt][2], acc[mt][nt][3]);
        }
    __syncthreads();

    {
        const int r = tid >> 1, half = tid & 1;
        const int grow = brow + r;
        const float* gr = gsm + r * GEPI_P + half * 64;
        const float* bcp = g_bc + bcol + half * 64;
        const int jbase = (bcol >> 2) + half * 16;
        float* cptr = g_C + (size_t)grow * HDIM + jbase;
        float cv[16];
#pragma unroll
        for (int q = 0; q < 4; q++) *(float4*)&cv[4 * q] = *(const float4*)&cptr[4 * q];
        union { __nv_bfloat16 b[16]; uint4 v[2]; } Hh, Hl;
#pragma unroll
        for (int jj = 0; jj < 16; jj++) {
            float gi = fsig(gr[4 * jj + 0] + bcp[4 * jj + 0]);
            float gf = fsig(gr[4 * jj + 1] + bcp[4 * jj + 1]);
            float gg = ftanh_fast(gr[4 * jj + 2] + bcp[4 * jj + 2]);
            float go = fsig(gr[4 * jj + 3] + bcp[4 * jj + 3]);
            float cn = gf * cv[jj] + gi * gg;
            cv[jj] = cn;
            float h = go * ftanh_fast(cn);
            split_bf16(h, Hh.b[jj], Hl.b[jj]);
        }
#pragma unroll
        for (int q = 0; q < 4; q++) *(float4*)&cptr[4 * q] = *(const float4*)&cv[4 * q];
        *(uint4*)&Anext[(size_t)grow * AW + jbase]            = Hh.v[0];
        *(uint4*)&Anext[(size_t)grow * AW + jbase + 8]        = Hh.v[1];
        *(uint4*)&Anext[(size_t)grow * AW + KSEG + jbase]     = Hl.v[0];
        *(uint4*)&Anext[(size_t)grow * AW + KSEG + jbase + 8] = Hl.v[1];
    }
}

// ---------------- output projection MMA kernel ----------------
// CTA tile 64x128 (N=V=128), K-tile 32, 3 stages. Grid = BATCH/64 = 128.
#define O_TILES    48            // 1536/32
#define O_STBLK    15360         // A(64x80)+B(128x80)
#define OS_SMEM    46080

__device__ __forceinline__ void out_fill(unsigned sb, int tid, int brow,
                                         const __nv_bfloat16* Abuf, int stage, int tile) {
    const int p = tile / 16, kk = tile - p * 16;
    const int acol = ((p == 2) ? KSEG : 0) + kk * 32;
    const int wcol = p * HDIM + kk * 32;
    const unsigned aBase = sb + stage * O_STBLK;
    const unsigned bBase = aBase + 5120u;
#pragma unroll
    for (int i = 0; i < 3; i++) {
        int cid = tid + (i << 8);            // 0..767
        int ch = cid & 3;
        if (cid < 256) {
            int r = cid >> 2;                // 0..63
            cp_async16(aBase + r * 80 + ch * 16,
                       Abuf + (size_t)(brow + r) * AW + acol + ch * 8);
        } else {
            int r = (cid - 256) >> 2;        // 0..127
            cp_async16(bBase + r * 80 + ch * 16,
                       g_Woext + (size_t)r * WOW + wcol + ch * 8);
        }
    }
    cp_commit();
}

__global__ void __launch_bounds__(256, 2) out_mma_kernel(int step, int par,
                                                         const float* __restrict__ bout,
                                                         float* __restrict__ out) {
    extern __shared__ char smem[];
    const unsigned sb = smem_u32(smem);
    const int tid = threadIdx.x, wid = tid >> 5, lane = tid & 31;
    const int warp_m = wid >> 2, warp_n = wid & 3;     // warp tile 32x32
    const int brow = blockIdx.x << 6;
    const __nv_bfloat16* Abuf = g_Abf[par];

    float acc[2][4][4];
#pragma unroll
    for (int i = 0; i < 2; i++)
#pragma unroll
        for (int j = 0; j < 4; j++)
#pragma unroll
            for (int q = 0; q < 4; q++) acc[i][j][q] = 0.0f;

    out_fill(sb, tid, brow, Abuf, 0, 0);
    out_fill(sb, tid, brow, Abuf, 1, 1);

    const int lrow = lane & 15;
    const int lkb  = (lane >> 4) * 16;

    for (int t = 0; t < O_TILES; t++) {
        if (t == O_TILES - 1) cp_wait<0>(); else cp_wait<1>();
        __syncthreads();
        int f = t + 2;
        if (f < O_TILES) out_fill(sb, tid, brow, Abuf, f % 3, f);

        const int s = t % 3;
        const unsigned aBase = sb + s * O_STBLK;
        const unsigned bBase = aBase + 5120u;
#pragma unroll
        for (int ks = 0; ks < 2; ks++) {
            const unsigned koff = ks * 32 + lkb;
            unsigned a[2][4], b[2][4];
#pragma unroll
            for (int mt = 0; mt < 2; mt++)
                ldsm4(a[mt][0], a[mt][1], a[mt][2], a[mt][3],
                      aBase + (warp_m * 32 + mt * 16 + lrow) * 80 + koff);
#pragma unroll
            for (int bt = 0; bt < 2; bt++)
                ldsm4(b[bt][0], b[bt][1], b[bt][2], b[bt][3],
                      bBase + (warp_n * 32 + bt * 16 + lrow) * 80 + koff);
#pragma unroll
            for (int mt = 0; mt < 2; mt++)
#pragma unroll
                for (int nt = 0; nt < 4; nt++) {
                    int bt = nt >> 1, sel = nt & 1;
                    mma16816(acc[mt][nt][0], acc[mt][nt][1], acc[mt][nt][2], acc[mt][nt][3],
                             a[mt][0], a[mt][1], a[mt][2], a[mt][3],
                             b[bt][sel], b[bt][sel + 2]);
                }
        }
    }

    // direct epilogue: bias + store
    const int row0 = lane >> 2, colq = (lane & 3) * 2;
    float* dstbase = out + (size_t)step * BATCH * VDIM;
#pragma unroll
    for (int mt = 0; mt < 2; mt++)
#pragma unroll
        for (int nt = 0; nt < 4; nt++) {
            int rs = brow + warp_m * 32 + mt * 16 + row0;
            int cs = warp_n * 32 + nt * 8 + colq;
            float2 bv = *(const float2*)&bout[cs];
            *(float2*)&dstbase[(size_t)rs * VDIM + cs] =
                make_float2(acc[mt][nt][0] + bv.x, acc[mt][nt][1] + bv.y);
            *(float2*)&dstbase[(size_t)(rs + 8) * VDIM + cs] =
                make_float2(acc[mt][nt][2] + bv.x, acc[mt][nt][3] + bv.y);
        }
}

// ---------------- tail: hT, cT ----------------
__global__ void final_kernel(float* __restrict__ out) {
    int idx = blockIdx.x * blockDim.x + threadIdx.x;
    if (idx >= BATCH * HDIM) return;
    int b = idx >> 9, j = idx & (HDIM - 1);
    size_t base = (size_t)L * BATCH * VDIM;
    float h = __bfloat162float(g_Abf[0][(size_t)b * AW + j]) +
              __bfloat162float(g_Abf[0][(size_t)b * AW + KSEG + j]);
    out[base + idx] = h;
    out[base + (size_t)BATCH * HDIM + idx] = g_C[idx];
}

// ---------------- launch ----------------
extern "C" void kernel_launch(void* const* d_in, const int* in_sizes, int n_in,
                              void* d_out, int out_size) {
    const int*   input = (const int*)d_in[0];
    const float* h0    = (const float*)d_in[1];
    const float* c0    = (const float*)d_in[2];
    const float* emb   = (const float*)d_in[3];
    const float* W_ih  = (const float*)d_in[4];
    const float* W_hh  = (const float*)d_in[5];
    const float* b_ih  = (const float*)d_in[6];
    const float* b_hh  = (const float*)d_in[7];
    const float* W_out = (const float*)d_in[8];
    const float* b_out = (const float*)d_in[9];
    float* out = (float*)d_out;

    cudaFuncSetAttribute(gates_mma_kernel, cudaFuncAttributeMaxDynamicSharedMemorySize, GS_SMEM);
    cudaFuncSetAttribute(out_mma_kernel,   cudaFuncAttributeMaxDynamicSharedMemorySize, OS_SMEM);

    long long wtot = (long long)G4H * WW;   // covers all three prep parts
    prep_all_kernel<<<(unsigned)((wtot + 255) / 256), 256>>>(W_ih, W_hh, W_out, b_ih, b_hh);
    init_kernel<<<(BATCH * HDIM + 255) / 256, 256>>>(h0, c0);

    dim3 ggrid(G4H / 128, BATCH / 128);     // (16, 64)
    for (int t = 0; t < L; t++) {
        xcopy_kernel<<<(BATCH * EDIM + 255) / 256, 256>>>(input, emb, t);
        gates_mma_kernel<<<ggrid, 256, GS_SMEM>>>(t & 1);
        out_mma_kernel<<<BATCH / 64, 256, OS_SMEM>>>(t, (t + 1) & 1, b_out, out);
    }
    final_kernel<<<(BATCH * HDIM + 255) / 256, 256>>>(out);
}